// round 12
// baseline (speedup 1.0000x reference)
#include <cuda_runtime.h>
#include <cuda_fp16.h>
#include <cstdint>
#include <math.h>

#define Bb 8
#define Tt 2048
#define Ee 2048
#define FFF 8192
#define MR (Bb * Tt)
#define EE (Ee * Ee)

// ---------------- scratch ---------------------------------------------------
__device__ float  g_s [(size_t)Bb * Tt * Tt];
__device__ float  g_x1[(size_t)MR * Ee];
__device__ __half g_hh [(size_t)MR * Ee];
__device__ __half g_qh [(size_t)MR * Ee];
__device__ __half g_kh [(size_t)MR * Ee];
__device__ __half g_vh [(size_t)MR * Ee];
__device__ __half g_ph [(size_t)Bb * Tt * Tt];
__device__ __half g_ath[(size_t)MR * Ee];
__device__ __half g_ffh[(size_t)MR * FFF];
__device__ __half g_wh [(size_t)4 * EE + 2 * (size_t)FFF * Ee];

// ---------------- helpers ----------------------------------------------------
__device__ __forceinline__ uint32_t smem_u32(const void* p) {
    uint32_t a;
    asm("{ .reg .u64 t; cvta.to.shared.u64 t, %1; cvt.u32.u64 %0, t; }" : "=r"(a) : "l"(p));
    return a;
}
#define CPA16(dst, src) asm volatile("cp.async.cg.shared.global [%0], [%1], 16;" :: "r"(dst), "l"(src))
#define CP_COMMIT()     asm volatile("cp.async.commit_group;" ::: "memory")
#define CP_WAIT(n)      asm volatile("cp.async.wait_group %0;" :: "n"(n) : "memory")

#define LDSM4(r0, r1, r2, r3, a)                                                \
    asm volatile("ldmatrix.sync.aligned.m8n8.x4.shared.b16 {%0,%1,%2,%3}, [%4];"\
        : "=r"(r0), "=r"(r1), "=r"(r2), "=r"(r3) : "r"(a))
#define LDSM4T(r0, r1, r2, r3, a)                                               \
    asm volatile("ldmatrix.sync.aligned.m8n8.x4.trans.shared.b16 {%0,%1,%2,%3}, [%4];"\
        : "=r"(r0), "=r"(r1), "=r"(r2), "=r"(r3) : "r"(a))
#define MMA16816(d, a, b)                                                       \
    asm volatile("mma.sync.aligned.m16n8k16.row.col.f32.f16.f16.f32 "           \
        "{%0,%1,%2,%3}, {%4,%5,%6,%7}, {%8,%9}, {%0,%1,%2,%3};"                 \
        : "+f"((d)[0]), "+f"((d)[1]), "+f"((d)[2]), "+f"((d)[3])                \
        : "r"((a)[0]), "r"((a)[1]), "r"((a)[2]), "r"((a)[3]),                   \
          "r"((b)[0]), "r"((b)[1]))

// ---------------- fp32 -> fp16 rounding converter ------------------------------
__global__ void cvt_kernel(const float* __restrict__ src,
                           __half* __restrict__ hi, int n)
{
    int i = (blockIdx.x * 256 + threadIdx.x) * 4;
    if (i >= n) return;
    float4 v = *(const float4*)(src + i);
    *(__half2*)(hi + i)     = __floats2half2_rn(v.x, v.y);
    *(__half2*)(hi + i + 2) = __floats2half2_rn(v.z, v.w);
}

// ---------------- fp16 HMMA GEMM, BK=32, cp.async 5-stage ring -----------------
// C = A * op(B), both fp16. NN=false: B [N,K] row-major. NN=true: B [K,N].
// EPI 0: fp32 C (+bias,res). EPI 1: fp16 C (+bias). RELU pre-round.
// causal: 1 = skip tiles above diagonal, 2 = clamp K at diagonal.
// stage: A [0,10240) rows 80B-stride; B [10240,20480) (NN: 272B-stride rows)
#define STAGE 20480
#define NSTG 5
#define HSMEM (STAGE * NSTG)

template<bool NN, int EPIPL, bool RELU>
__global__ void __launch_bounds__(256, 2) hgemm(
    const __half* __restrict__ Ah, const __half* __restrict__ Bh,
    const float* __restrict__ bias, const float* __restrict__ res,
    float* __restrict__ C, __half* __restrict__ Ch,
    int N, int K, size_t sA, size_t sB, size_t sC, int causal)
{
    int m0 = blockIdx.y * 128, n0 = blockIdx.x * 128;
    if (causal == 1 && n0 > m0) return;
    size_t zo = (size_t)blockIdx.z;
    Ah += zo * sA;
    Bh += zo * sB;
    if (EPIPL) Ch += zo * sC;
    else       C  += zo * sC;

    extern __shared__ char sm[];
    uint32_t sb = smem_u32(sm);
    int tid = threadIdx.x, lane = tid & 31, wid = tid >> 5;
    int wm = (wid & 3) * 32, wn = (wid >> 2) * 64;

    int kend = K;
    if (causal == 2) { int l = m0 + 128; kend = (l < K) ? l : K; }
    int nch = kend >> 5;

    float c[2][8][4];
    #pragma unroll
    for (int i = 0; i < 2; i++)
        #pragma unroll
        for (int j = 0; j < 8; j++)
            #pragma unroll
            for (int q = 0; q < 4; q++) c[i][j][q] = 0.f;

    // issue one BK=32 chunk's loads into smem stage via cp.async
    auto issue = [&](int ch, int stg) {
        int k0 = ch << 5;
        uint32_t st = sb + (uint32_t)stg * STAGE;
        #pragma unroll
        for (int i = 0; i < 2; i++) {
            int id = tid + (i << 8);
            int row = id >> 2, c4 = id & 3;            // 128 rows x 4 chunks
            CPA16(st + row * 80 + (c4 << 4),
                  Ah + (size_t)(m0 + row) * K + k0 + (c4 << 3));
            if (NN) {
                int rw = id >> 4, cc = id & 15;        // 32 k-rows x 16 chunks
                CPA16(st + 10240 + rw * 272 + (cc << 4),
                      Bh + (size_t)(k0 + rw) * N + n0 + (cc << 3));
            } else {
                CPA16(st + 10240 + row * 80 + (c4 << 4),
                      Bh + (size_t)(n0 + row) * K + k0 + (c4 << 3));
            }
        }
    };

    uint32_t aOff   = (uint32_t)((wm + (lane & 15)) * 80 + (lane >> 4) * 16);
    uint32_t bOffNT = (uint32_t)(10240 + (wn + (lane & 7) + ((lane >> 4) << 3)) * 80
                                 + ((lane >> 3) & 1) * 16);
    uint32_t bOffNN = (uint32_t)(10240 + ((lane & 7) + (((lane >> 3) & 1) << 3)) * 272
                                 + (wn + ((lane >> 4) << 3)) * 2);

    // prologue: up to 4 stages in flight
    #pragma unroll
    for (int s = 0; s < NSTG - 1; s++) {
        if (s < nch) issue(s, s);
        CP_COMMIT();
    }

    int stg = 0;
    for (int ch = 0; ch < nch; ch++) {
        CP_WAIT(3);               // group for chunk ch has landed
        __syncthreads();          // all warps done with the stage about to be refilled
        if (ch + NSTG - 1 < nch) {
            int ns = stg + NSTG - 1; if (ns >= NSTG) ns -= NSTG;
            issue(ch + NSTG - 1, ns);
        }
        CP_COMMIT();

        uint32_t base = sb + (uint32_t)stg * STAGE;
        #pragma unroll
        for (int ks = 0; ks < 2; ks++) {
            uint32_t ah[2][4], bh[8][2];
            #pragma unroll
            for (int mt = 0; mt < 2; mt++) {
                uint32_t ad = base + aOff + mt * 1280 + ks * 32;
                LDSM4(ah[mt][0], ah[mt][1], ah[mt][2], ah[mt][3], ad);
            }
            #pragma unroll
            for (int p = 0; p < 4; p++) {
                if (NN) {
                    uint32_t bd = base + bOffNN + ks * 4352 + p * 32;
                    LDSM4T(bh[2*p][0], bh[2*p][1], bh[2*p+1][0], bh[2*p+1][1], bd);
                } else {
                    uint32_t bd = base + bOffNT + p * 1280 + ks * 32;
                    LDSM4(bh[2*p][0], bh[2*p][1], bh[2*p+1][0], bh[2*p+1][1], bd);
                }
            }
            #pragma unroll
            for (int mt = 0; mt < 2; mt++)
                #pragma unroll
                for (int nt = 0; nt < 8; nt++)
                    MMA16816(c[mt][nt], ah[mt], bh[nt]);
        }
        stg = (stg + 1 >= NSTG) ? 0 : stg + 1;
    }

    // epilogue
    int g = lane >> 2, tg = lane & 3;
    #pragma unroll
    for (int mt = 0; mt < 2; mt++) {
        #pragma unroll
        for (int nt = 0; nt < 8; nt++) {
            int n = n0 + wn + nt * 8 + tg * 2;
            #pragma unroll
            for (int hr = 0; hr < 2; hr++) {
                int m = m0 + wm + mt * 16 + g + hr * 8;
                float v0 = c[mt][nt][hr * 2 + 0], v1 = c[mt][nt][hr * 2 + 1];
                if (bias) { v0 += __ldg(&bias[n]); v1 += __ldg(&bias[n + 1]); }
                if (RELU) { v0 = fmaxf(v0, 0.f); v1 = fmaxf(v1, 0.f); }
                if (EPIPL) {
                    *(__half2*)(Ch + (size_t)m * N + n) = __floats2half2_rn(v0, v1);
                } else {
                    if (res) {
                        float2 r = *(const float2*)(res + (size_t)m * N + n);
                        v0 += r.x; v1 += r.y;
                    }
                    *(float2*)(C + (size_t)m * N + n) = make_float2(v0, v1);
                }
            }
        }
    }
}

// ---------------- LayerNorm -> fp16 -------------------------------------------
__global__ void ln_kernel(const float* __restrict__ x,
                          const float* __restrict__ gamma,
                          const float* __restrict__ beta,
                          __half* __restrict__ oh)
{
    int row = blockIdx.x;
    const float* xr = x + (size_t)row * Ee;
    float s = 0.f, s2 = 0.f;
    for (int i = threadIdx.x; i < Ee; i += 256) {
        float v = xr[i]; s += v; s2 += v * v;
    }
    __shared__ float sh[64];
    #pragma unroll
    for (int off = 16; off; off >>= 1) {
        s  += __shfl_xor_sync(0xffffffffu, s,  off);
        s2 += __shfl_xor_sync(0xffffffffu, s2, off);
    }
    int w = threadIdx.x >> 5, lane = threadIdx.x & 31;
    if (lane == 0) { sh[w] = s; sh[32 + w] = s2; }
    __syncthreads();
    if (w == 0) {
        s  = (lane < 8) ? sh[lane] : 0.f;
        s2 = (lane < 8) ? sh[32 + lane] : 0.f;
        #pragma unroll
        for (int off = 4; off; off >>= 1) {
            s  += __shfl_xor_sync(0xffffffffu, s,  off);
            s2 += __shfl_xor_sync(0xffffffffu, s2, off);
        }
        if (lane == 0) { sh[0] = s; sh[1] = s2; }
    }
    __syncthreads();
    float mean = sh[0] * (1.f / Ee);
    float var  = sh[1] * (1.f / Ee) - mean * mean;
    float inv  = rsqrtf(var + 1e-5f);
    for (int i = threadIdx.x; i < Ee; i += 256) {
        float y = (xr[i] - mean) * inv * gamma[i] + beta[i];
        oh[(size_t)row * Ee + i] = __float2half_rn(y);
    }
}

// ---------------- causal softmax -> fp16 ---------------------------------------
__global__ void softmax_kernel(const float* __restrict__ S, __half* __restrict__ ph)
{
    int t = blockIdx.x, b = blockIdx.y;
    const float* row = S + ((size_t)b * Tt + t) * Tt;
    __half* prh = ph + ((size_t)b * Tt + t) * Tt;
    int n = t + 1;
    const float scale = 0.0220970869120796101f;  // 1/sqrt(2048)
    __shared__ float sh[32];
    int w = threadIdx.x >> 5, lane = threadIdx.x & 31;

    float mx = -3.4e38f;
    for (int i = threadIdx.x; i < n; i += 256) mx = fmaxf(mx, row[i]);
    #pragma unroll
    for (int off = 16; off; off >>= 1) mx = fmaxf(mx, __shfl_xor_sync(0xffffffffu, mx, off));
    if (lane == 0) sh[w] = mx;
    __syncthreads();
    if (w == 0) {
        mx = (lane < 8) ? sh[lane] : -3.4e38f;
        #pragma unroll
        for (int off = 4; off; off >>= 1) mx = fmaxf(mx, __shfl_xor_sync(0xffffffffu, mx, off));
        if (lane == 0) sh[0] = mx;
    }
    __syncthreads();
    mx = sh[0];
    __syncthreads();

    float sum = 0.f;
    for (int i = threadIdx.x; i < n; i += 256) sum += __expf((row[i] - mx) * scale);
    #pragma unroll
    for (int off = 16; off; off >>= 1) sum += __shfl_xor_sync(0xffffffffu, sum, off);
    if (lane == 0) sh[w] = sum;
    __syncthreads();
    if (w == 0) {
        sum = (lane < 8) ? sh[lane] : 0.f;
        #pragma unroll
        for (int off = 4; off; off >>= 1) sum += __shfl_xor_sync(0xffffffffu, sum, off);
        if (lane == 0) sh[0] = sum;
    }
    __syncthreads();
    float inv = 1.f / sh[0];
    for (int i = threadIdx.x; i < Tt; i += 256) {
        float p = (i < n) ? __expf((row[i] - mx) * scale) * inv : 0.f;
        prh[i] = __float2half_rn(p);
    }
}

// ---------------- launch -------------------------------------------------------
extern "C" void kernel_launch(void* const* d_in, const int* in_sizes, int n_in,
                              void* d_out, int out_size)
{
    const float* x      = (const float*)d_in[0];
    const float* gamma1 = (const float*)d_in[1];
    const float* beta1  = (const float*)d_in[2];
    const float* Wq     = (const float*)d_in[3];
    const float* Wk     = (const float*)d_in[4];
    const float* Wv     = (const float*)d_in[5];
    const float* Wo     = (const float*)d_in[6];
    const float* bo     = (const float*)d_in[7];
    const float* gamma2 = (const float*)d_in[8];
    const float* beta2  = (const float*)d_in[9];
    const float* W1     = (const float*)d_in[10];
    const float* b1     = (const float*)d_in[11];
    const float* W2     = (const float*)d_in[12];
    const float* b2     = (const float*)d_in[13];
    float* out = (float*)d_out;

    float *s, *x1;
    __half *hh, *qh, *kh, *vh, *ph, *ath, *ffh, *wh;
    cudaGetSymbolAddress((void**)&s,   g_s);
    cudaGetSymbolAddress((void**)&x1,  g_x1);
    cudaGetSymbolAddress((void**)&hh,  g_hh);
    cudaGetSymbolAddress((void**)&qh,  g_qh);
    cudaGetSymbolAddress((void**)&kh,  g_kh);
    cudaGetSymbolAddress((void**)&vh,  g_vh);
    cudaGetSymbolAddress((void**)&ph,  g_ph);
    cudaGetSymbolAddress((void**)&ath, g_ath);
    cudaGetSymbolAddress((void**)&ffh, g_ffh);
    cudaGetSymbolAddress((void**)&wh,  g_wh);

    cudaFuncSetAttribute(hgemm<false, 0, false>, cudaFuncAttributeMaxDynamicSharedMemorySize, HSMEM);
    cudaFuncSetAttribute(hgemm<false, 1, false>, cudaFuncAttributeMaxDynamicSharedMemorySize, HSMEM);
    cudaFuncSetAttribute(hgemm<false, 1, true>,  cudaFuncAttributeMaxDynamicSharedMemorySize, HSMEM);
    cudaFuncSetAttribute(hgemm<true,  1, false>, cudaFuncAttributeMaxDynamicSharedMemorySize, HSMEM);

    const size_t oW1 = (size_t)4 * EE, oW2 = (size_t)4 * EE + (size_t)FFF * Ee;

    // 0) weight rounding (fp32 -> fp16)
    cvt_kernel<<<EE / 1024, 256>>>(Wq, wh,          EE);
    cvt_kernel<<<EE / 1024, 256>>>(Wk, wh + EE,     EE);
    cvt_kernel<<<EE / 1024, 256>>>(Wv, wh + 2 * EE, EE);
    cvt_kernel<<<EE / 1024, 256>>>(Wo, wh + 3 * EE, EE);
    cvt_kernel<<<FFF * Ee / 1024, 256>>>(W1, wh + oW1, FFF * Ee);
    cvt_kernel<<<FFF * Ee / 1024, 256>>>(W2, wh + oW2, FFF * Ee);

    // 1) LN1 -> fp16
    ln_kernel<<<MR, 256>>>(x, gamma1, beta1, hh);

    // 2) QKV projections -> fp16
    dim3 gProj(Ee / 128, MR / 128, 1);
    hgemm<false, 1, false><<<gProj, 256, HSMEM>>>(hh, wh,          nullptr, nullptr, nullptr, qh, Ee, Ee, 0, 0, 0, 0);
    hgemm<false, 1, false><<<gProj, 256, HSMEM>>>(hh, wh + EE,     nullptr, nullptr, nullptr, kh, Ee, Ee, 0, 0, 0, 0);
    hgemm<false, 1, false><<<gProj, 256, HSMEM>>>(hh, wh + 2 * EE, nullptr, nullptr, nullptr, vh, Ee, Ee, 0, 0, 0, 0);

    // 3) S = q k^T (fp32 out, causal tile skip)
    dim3 gQK(Tt / 128, Tt / 128, Bb);
    hgemm<false, 0, false><<<gQK, 256, HSMEM>>>(qh, kh, nullptr, nullptr, s, nullptr,
                                                Tt, Ee, (size_t)Tt * Ee, (size_t)Tt * Ee, (size_t)Tt * Tt, 1);

    // 4) causal softmax -> fp16 probs
    softmax_kernel<<<dim3(Tt, Bb), 256>>>(s, ph);

    // 5) attn = P @ V (NN, K clamped at diagonal) -> fp16
    dim3 gPV(Ee / 128, Tt / 128, Bb);
    hgemm<true, 1, false><<<gPV, 256, HSMEM>>>(ph, vh, nullptr, nullptr, nullptr, ath,
                                               Ee, Tt, (size_t)Tt * Tt, (size_t)Tt * Ee, (size_t)Tt * Ee, 2);

    // 6) x1 = attn Wo^T + bo + x (fp32)
    hgemm<false, 0, false><<<gProj, 256, HSMEM>>>(ath, wh + 3 * EE, bo, x, x1, nullptr,
                                                  Ee, Ee, 0, 0, 0, 0);

    // 7) LN2 -> fp16
    ln_kernel<<<MR, 256>>>(x1, gamma2, beta2, hh);

    // 8) ff = relu(h W1^T + b1) -> fp16
    dim3 gFF1(FFF / 128, MR / 128, 1);
    hgemm<false, 1, true><<<gFF1, 256, HSMEM>>>(hh, wh + oW1, b1, nullptr, nullptr, ffh,
                                                FFF, Ee, 0, 0, 0, 0);

    // 9) out = ff W2^T + b2 + x1 (fp32)
    dim3 gFF2(Ee / 128, MR / 128, 1);
    hgemm<false, 0, false><<<gFF2, 256, HSMEM>>>(ffh, wh + oW2, b2, x1, out, nullptr,
                                                 Ee, FFF, 0, 0, 0, 0);
}

// round 13
// speedup vs baseline: 1.0615x; 1.0615x over previous
#include <cuda_runtime.h>
#include <cuda_fp16.h>
#include <cstdint>
#include <math.h>

#define Bb 8
#define Tt 2048
#define Ee 2048
#define FFF 8192
#define MR (Bb * Tt)
#define EE (Ee * Ee)

// ---------------- scratch ---------------------------------------------------
__device__ float  g_s [(size_t)Bb * Tt * Tt];
__device__ float  g_x1[(size_t)MR * Ee];
__device__ __half g_hh [(size_t)MR * Ee];
__device__ __half g_qh [(size_t)MR * Ee];
__device__ __half g_kh [(size_t)MR * Ee];
__device__ __half g_vh [(size_t)MR * Ee];
__device__ __half g_ph [(size_t)Bb * Tt * Tt];
__device__ __half g_ath[(size_t)MR * Ee];
__device__ __half g_ffh[(size_t)MR * FFF];
__device__ __half g_wh [(size_t)4 * EE + 2 * (size_t)FFF * Ee];

// ---------------- helpers ----------------------------------------------------
__device__ __forceinline__ uint32_t smem_u32(const void* p) {
    uint32_t a;
    asm("{ .reg .u64 t; cvta.to.shared.u64 t, %1; cvt.u32.u64 %0, t; }" : "=r"(a) : "l"(p));
    return a;
}
#define CPA16(dst, src) asm volatile("cp.async.cg.shared.global [%0], [%1], 16;" :: "r"(dst), "l"(src))
#define CP_COMMIT()     asm volatile("cp.async.commit_group;" ::: "memory")
#define CP_WAIT(n)      asm volatile("cp.async.wait_group %0;" :: "n"(n) : "memory")

#define LDSM4(r0, r1, r2, r3, a)                                                \
    asm volatile("ldmatrix.sync.aligned.m8n8.x4.shared.b16 {%0,%1,%2,%3}, [%4];"\
        : "=r"(r0), "=r"(r1), "=r"(r2), "=r"(r3) : "r"(a))
#define LDSM4T(r0, r1, r2, r3, a)                                               \
    asm volatile("ldmatrix.sync.aligned.m8n8.x4.trans.shared.b16 {%0,%1,%2,%3}, [%4];"\
        : "=r"(r0), "=r"(r1), "=r"(r2), "=r"(r3) : "r"(a))
#define MMA16816(d, a, b)                                                       \
    asm volatile("mma.sync.aligned.m16n8k16.row.col.f32.f16.f16.f32 "           \
        "{%0,%1,%2,%3}, {%4,%5,%6,%7}, {%8,%9}, {%0,%1,%2,%3};"                 \
        : "+f"((d)[0]), "+f"((d)[1]), "+f"((d)[2]), "+f"((d)[3])                \
        : "r"((a)[0]), "r"((a)[1]), "r"((a)[2]), "r"((a)[3]),                   \
          "r"((b)[0]), "r"((b)[1]))

// ---------------- fp32 -> fp16 rounding converter ------------------------------
__global__ void cvt_kernel(const float* __restrict__ src,
                           __half* __restrict__ hi, int n)
{
    int i = (blockIdx.x * 256 + threadIdx.x) * 4;
    if (i >= n) return;
    float4 v = *(const float4*)(src + i);
    *(__half2*)(hi + i)     = __floats2half2_rn(v.x, v.y);
    *(__half2*)(hi + i + 2) = __floats2half2_rn(v.z, v.w);
}

// ---------------- fp16 HMMA GEMM, BK=64, cp.async 3-stage + frag pipeline ------
// C = A * op(B), both fp16. NN=false: B [N,K] row-major. NN=true: B [K,N].
// EPI 0: fp32 C (+bias,res). EPI 1: fp16 C (+bias). RELU pre-round.
// causal: 1 = skip tiles above diagonal, 2 = clamp K at diagonal.
// stage: A [0,18432) rows 144B-stride; B [18432,36864) (NN: 272B-stride rows)
#define STAGE 36864
#define NSTG 3
#define HSMEM (STAGE * NSTG)

template<bool NN, int EPIPL, bool RELU>
__global__ void __launch_bounds__(256, 2) hgemm(
    const __half* __restrict__ Ah, const __half* __restrict__ Bh,
    const float* __restrict__ bias, const float* __restrict__ res,
    float* __restrict__ C, __half* __restrict__ Ch,
    int N, int K, size_t sA, size_t sB, size_t sC, int causal)
{
    int m0 = blockIdx.y * 128, n0 = blockIdx.x * 128;
    if (causal == 1 && n0 > m0) return;
    size_t zo = (size_t)blockIdx.z;
    Ah += zo * sA;
    Bh += zo * sB;
    if (EPIPL) Ch += zo * sC;
    else       C  += zo * sC;

    extern __shared__ char sm[];
    uint32_t sb = smem_u32(sm);
    int tid = threadIdx.x, lane = tid & 31, wid = tid >> 5;
    int wm = (wid & 3) * 32, wn = (wid >> 2) * 64;

    int kend = K;
    if (causal == 2) { int l = m0 + 128; kend = (l < K) ? l : K; }
    int nch = kend >> 6;

    float c[2][8][4];
    #pragma unroll
    for (int i = 0; i < 2; i++)
        #pragma unroll
        for (int j = 0; j < 8; j++)
            #pragma unroll
            for (int q = 0; q < 4; q++) c[i][j][q] = 0.f;

    // issue one chunk's loads straight into smem stage via cp.async
    auto issue = [&](int ch, int stg) {
        int k0 = ch << 6;
        uint32_t st = sb + (uint32_t)stg * STAGE;
        #pragma unroll
        for (int i = 0; i < 4; i++) {
            int id = tid + (i << 8);
            int row = id >> 3, c16 = id & 7;           // 128 rows x 8 chunks
            CPA16(st + row * 144 + (c16 << 4),
                  Ah + (size_t)(m0 + row) * K + k0 + (c16 << 3));
            if (NN) {
                int rw = id >> 4, cc = id & 15;        // 64 k-rows x 16 chunks
                CPA16(st + 18432 + rw * 272 + (cc << 4),
                      Bh + (size_t)(k0 + rw) * N + n0 + (cc << 3));
            } else {
                CPA16(st + 18432 + row * 144 + (c16 << 4),
                      Bh + (size_t)(n0 + row) * K + k0 + (c16 << 3));
            }
        }
    };

    uint32_t aOff   = (uint32_t)((wm + (lane & 15)) * 144 + (lane >> 4) * 16);
    uint32_t bOffNT = (uint32_t)(18432 + (wn + (lane & 7) + ((lane >> 4) << 3)) * 144
                                 + ((lane >> 3) & 1) * 16);
    uint32_t bOffNN = (uint32_t)(18432 + ((lane & 7) + (((lane >> 3) & 1) << 3)) * 272
                                 + (wn + ((lane >> 4) << 3)) * 2);

    // double-buffered fragments
    uint32_t ah[2][2][4], bh[2][8][2];

    auto ldfrag = [&](uint32_t base, int ks, int buf) {
        #pragma unroll
        for (int mt = 0; mt < 2; mt++) {
            uint32_t ad = base + aOff + mt * 2304 + ks * 32;
            LDSM4(ah[buf][mt][0], ah[buf][mt][1], ah[buf][mt][2], ah[buf][mt][3], ad);
        }
        #pragma unroll
        for (int p = 0; p < 4; p++) {
            if (NN) {
                uint32_t bd = base + bOffNN + ks * 4352 + p * 32;
                LDSM4T(bh[buf][2*p][0], bh[buf][2*p][1], bh[buf][2*p+1][0], bh[buf][2*p+1][1], bd);
            } else {
                uint32_t bd = base + bOffNT + p * 2304 + ks * 32;
                LDSM4(bh[buf][2*p][0], bh[buf][2*p][1], bh[buf][2*p+1][0], bh[buf][2*p+1][1], bd);
            }
        }
    };

    // prologue: 2 stages in flight
    issue(0, 0); CP_COMMIT();
    if (nch > 1) issue(1, 1);
    CP_COMMIT();

    int stg = 0;
    for (int ch = 0; ch < nch; ch++) {
        CP_WAIT(1);               // stage for chunk ch has landed
        __syncthreads();          // all warps done with the stage being refilled
        if (ch + 2 < nch) issue(ch + 2, (stg + 2 >= NSTG) ? stg + 2 - NSTG : stg + 2);
        CP_COMMIT();

        uint32_t base = sb + (uint32_t)stg * STAGE;
        ldfrag(base, 0, 0);
        #pragma unroll
        for (int ks = 0; ks < 4; ks++) {
            int cur = ks & 1;
            if (ks < 3) ldfrag(base, ks + 1, cur ^ 1);
            #pragma unroll
            for (int mt = 0; mt < 2; mt++)
                #pragma unroll
                for (int nt = 0; nt < 8; nt++)
                    MMA16816(c[mt][nt], ah[cur][mt], bh[cur][nt]);
        }
        stg = (stg + 1 >= NSTG) ? 0 : stg + 1;
    }

    // epilogue
    int g = lane >> 2, tg = lane & 3;
    #pragma unroll
    for (int mt = 0; mt < 2; mt++) {
        #pragma unroll
        for (int nt = 0; nt < 8; nt++) {
            int n = n0 + wn + nt * 8 + tg * 2;
            #pragma unroll
            for (int hr = 0; hr < 2; hr++) {
                int m = m0 + wm + mt * 16 + g + hr * 8;
                float v0 = c[mt][nt][hr * 2 + 0], v1 = c[mt][nt][hr * 2 + 1];
                if (bias) { v0 += __ldg(&bias[n]); v1 += __ldg(&bias[n + 1]); }
                if (RELU) { v0 = fmaxf(v0, 0.f); v1 = fmaxf(v1, 0.f); }
                if (EPIPL) {
                    *(__half2*)(Ch + (size_t)m * N + n) = __floats2half2_rn(v0, v1);
                } else {
                    if (res) {
                        float2 r = *(const float2*)(res + (size_t)m * N + n);
                        v0 += r.x; v1 += r.y;
                    }
                    *(float2*)(C + (size_t)m * N + n) = make_float2(v0, v1);
                }
            }
        }
    }
}

// ---------------- LayerNorm -> fp16 -------------------------------------------
__global__ void ln_kernel(const float* __restrict__ x,
                          const float* __restrict__ gamma,
                          const float* __restrict__ beta,
                          __half* __restrict__ oh)
{
    int row = blockIdx.x;
    const float* xr = x + (size_t)row * Ee;
    float s = 0.f, s2 = 0.f;
    for (int i = threadIdx.x; i < Ee; i += 256) {
        float v = xr[i]; s += v; s2 += v * v;
    }
    __shared__ float sh[64];
    #pragma unroll
    for (int off = 16; off; off >>= 1) {
        s  += __shfl_xor_sync(0xffffffffu, s,  off);
        s2 += __shfl_xor_sync(0xffffffffu, s2, off);
    }
    int w = threadIdx.x >> 5, lane = threadIdx.x & 31;
    if (lane == 0) { sh[w] = s; sh[32 + w] = s2; }
    __syncthreads();
    if (w == 0) {
        s  = (lane < 8) ? sh[lane] : 0.f;
        s2 = (lane < 8) ? sh[32 + lane] : 0.f;
        #pragma unroll
        for (int off = 4; off; off >>= 1) {
            s  += __shfl_xor_sync(0xffffffffu, s,  off);
            s2 += __shfl_xor_sync(0xffffffffu, s2, off);
        }
        if (lane == 0) { sh[0] = s; sh[1] = s2; }
    }
    __syncthreads();
    float mean = sh[0] * (1.f / Ee);
    float var  = sh[1] * (1.f / Ee) - mean * mean;
    float inv  = rsqrtf(var + 1e-5f);
    for (int i = threadIdx.x; i < Ee; i += 256) {
        float y = (xr[i] - mean) * inv * gamma[i] + beta[i];
        oh[(size_t)row * Ee + i] = __float2half_rn(y);
    }
}

// ---------------- causal softmax -> fp16 ---------------------------------------
__global__ void softmax_kernel(const float* __restrict__ S, __half* __restrict__ ph)
{
    int t = blockIdx.x, b = blockIdx.y;
    const float* row = S + ((size_t)b * Tt + t) * Tt;
    __half* prh = ph + ((size_t)b * Tt + t) * Tt;
    int n = t + 1;
    const float scale = 0.0220970869120796101f;  // 1/sqrt(2048)
    __shared__ float sh[32];
    int w = threadIdx.x >> 5, lane = threadIdx.x & 31;

    float mx = -3.4e38f;
    for (int i = threadIdx.x; i < n; i += 256) mx = fmaxf(mx, row[i]);
    #pragma unroll
    for (int off = 16; off; off >>= 1) mx = fmaxf(mx, __shfl_xor_sync(0xffffffffu, mx, off));
    if (lane == 0) sh[w] = mx;
    __syncthreads();
    if (w == 0) {
        mx = (lane < 8) ? sh[lane] : -3.4e38f;
        #pragma unroll
        for (int off = 4; off; off >>= 1) mx = fmaxf(mx, __shfl_xor_sync(0xffffffffu, mx, off));
        if (lane == 0) sh[0] = mx;
    }
    __syncthreads();
    mx = sh[0];
    __syncthreads();

    float sum = 0.f;
    for (int i = threadIdx.x; i < n; i += 256) sum += __expf((row[i] - mx) * scale);
    #pragma unroll
    for (int off = 16; off; off >>= 1) sum += __shfl_xor_sync(0xffffffffu, sum, off);
    if (lane == 0) sh[w] = sum;
    __syncthreads();
    if (w == 0) {
        sum = (lane < 8) ? sh[lane] : 0.f;
        #pragma unroll
        for (int off = 4; off; off >>= 1) sum += __shfl_xor_sync(0xffffffffu, sum, off);
        if (lane == 0) sh[0] = sum;
    }
    __syncthreads();
    float inv = 1.f / sh[0];
    for (int i = threadIdx.x; i < Tt; i += 256) {
        float p = (i < n) ? __expf((row[i] - mx) * scale) * inv : 0.f;
        prh[i] = __float2half_rn(p);
    }
}

// ---------------- launch -------------------------------------------------------
extern "C" void kernel_launch(void* const* d_in, const int* in_sizes, int n_in,
                              void* d_out, int out_size)
{
    const float* x      = (const float*)d_in[0];
    const float* gamma1 = (const float*)d_in[1];
    const float* beta1  = (const float*)d_in[2];
    const float* Wq     = (const float*)d_in[3];
    const float* Wk     = (const float*)d_in[4];
    const float* Wv     = (const float*)d_in[5];
    const float* Wo     = (const float*)d_in[6];
    const float* bo     = (const float*)d_in[7];
    const float* gamma2 = (const float*)d_in[8];
    const float* beta2  = (const float*)d_in[9];
    const float* W1     = (const float*)d_in[10];
    const float* b1     = (const float*)d_in[11];
    const float* W2     = (const float*)d_in[12];
    const float* b2     = (const float*)d_in[13];
    float* out = (float*)d_out;

    float *s, *x1;
    __half *hh, *qh, *kh, *vh, *ph, *ath, *ffh, *wh;
    cudaGetSymbolAddress((void**)&s,   g_s);
    cudaGetSymbolAddress((void**)&x1,  g_x1);
    cudaGetSymbolAddress((void**)&hh,  g_hh);
    cudaGetSymbolAddress((void**)&qh,  g_qh);
    cudaGetSymbolAddress((void**)&kh,  g_kh);
    cudaGetSymbolAddress((void**)&vh,  g_vh);
    cudaGetSymbolAddress((void**)&ph,  g_ph);
    cudaGetSymbolAddress((void**)&ath, g_ath);
    cudaGetSymbolAddress((void**)&ffh, g_ffh);
    cudaGetSymbolAddress((void**)&wh,  g_wh);

    cudaFuncSetAttribute(hgemm<false, 0, false>, cudaFuncAttributeMaxDynamicSharedMemorySize, HSMEM);
    cudaFuncSetAttribute(hgemm<false, 1, false>, cudaFuncAttributeMaxDynamicSharedMemorySize, HSMEM);
    cudaFuncSetAttribute(hgemm<false, 1, true>,  cudaFuncAttributeMaxDynamicSharedMemorySize, HSMEM);
    cudaFuncSetAttribute(hgemm<true,  1, false>, cudaFuncAttributeMaxDynamicSharedMemorySize, HSMEM);

    const size_t oW1 = (size_t)4 * EE, oW2 = (size_t)4 * EE + (size_t)FFF * Ee;

    // 0) weight rounding (fp32 -> fp16)
    cvt_kernel<<<EE / 1024, 256>>>(Wq, wh,          EE);
    cvt_kernel<<<EE / 1024, 256>>>(Wk, wh + EE,     EE);
    cvt_kernel<<<EE / 1024, 256>>>(Wv, wh + 2 * EE, EE);
    cvt_kernel<<<EE / 1024, 256>>>(Wo, wh + 3 * EE, EE);
    cvt_kernel<<<FFF * Ee / 1024, 256>>>(W1, wh + oW1, FFF * Ee);
    cvt_kernel<<<FFF * Ee / 1024, 256>>>(W2, wh + oW2, FFF * Ee);

    // 1) LN1 -> fp16
    ln_kernel<<<MR, 256>>>(x, gamma1, beta1, hh);

    // 2) QKV projections -> fp16
    dim3 gProj(Ee / 128, MR / 128, 1);
    hgemm<false, 1, false><<<gProj, 256, HSMEM>>>(hh, wh,          nullptr, nullptr, nullptr, qh, Ee, Ee, 0, 0, 0, 0);
    hgemm<false, 1, false><<<gProj, 256, HSMEM>>>(hh, wh + EE,     nullptr, nullptr, nullptr, kh, Ee, Ee, 0, 0, 0, 0);
    hgemm<false, 1, false><<<gProj, 256, HSMEM>>>(hh, wh + 2 * EE, nullptr, nullptr, nullptr, vh, Ee, Ee, 0, 0, 0, 0);

    // 3) S = q k^T (fp32 out, causal tile skip)
    dim3 gQK(Tt / 128, Tt / 128, Bb);
    hgemm<false, 0, false><<<gQK, 256, HSMEM>>>(qh, kh, nullptr, nullptr, s, nullptr,
                                                Tt, Ee, (size_t)Tt * Ee, (size_t)Tt * Ee, (size_t)Tt * Tt, 1);

    // 4) causal softmax -> fp16 probs
    softmax_kernel<<<dim3(Tt, Bb), 256>>>(s, ph);

    // 5) attn = P @ V (NN, K clamped at diagonal) -> fp16
    dim3 gPV(Ee / 128, Tt / 128, Bb);
    hgemm<true, 1, false><<<gPV, 256, HSMEM>>>(ph, vh, nullptr, nullptr, nullptr, ath,
                                               Ee, Tt, (size_t)Tt * Tt, (size_t)Tt * Ee, (size_t)Tt * Ee, 2);

    // 6) x1 = attn Wo^T + bo + x (fp32)
    hgemm<false, 0, false><<<gProj, 256, HSMEM>>>(ath, wh + 3 * EE, bo, x, x1, nullptr,
                                                  Ee, Ee, 0, 0, 0, 0);

    // 7) LN2 -> fp16
    ln_kernel<<<MR, 256>>>(x1, gamma2, beta2, hh);

    // 8) ff = relu(h W1^T + b1) -> fp16
    dim3 gFF1(FFF / 128, MR / 128, 1);
    hgemm<false, 1, true><<<gFF1, 256, HSMEM>>>(hh, wh + oW1, b1, nullptr, nullptr, ffh,
                                                FFF, Ee, 0, 0, 0, 0);

    // 9) out = ff W2^T + b2 + x1 (fp32)
    dim3 gFF2(Ee / 128, MR / 128, 1);
    hgemm<false, 0, false><<<gFF2, 256, HSMEM>>>(ffh, wh + oW2, b2, x1, out, nullptr,
                                                 Ee, FFF, 0, 0, 0, 0);
}

// round 14
// speedup vs baseline: 1.0808x; 1.0182x over previous
#include <cuda_runtime.h>
#include <cuda_fp16.h>
#include <cstdint>
#include <math.h>

#define Bb 8
#define Tt 2048
#define Ee 2048
#define FFF 8192
#define MR (Bb * Tt)
#define EE (Ee * Ee)
#define QKVN (3 * Ee)   // 6144

// ---------------- scratch ---------------------------------------------------
__device__ float  g_s  [(size_t)Bb * Tt * Tt];
__device__ float  g_x1 [(size_t)MR * Ee];
__device__ __half g_hh [(size_t)MR * Ee];
__device__ __half g_qkv[(size_t)MR * QKVN];
__device__ __half g_ph [(size_t)Bb * Tt * Tt];
__device__ __half g_ath[(size_t)MR * Ee];
__device__ __half g_ffh[(size_t)MR * FFF];
__device__ __half g_wh [(size_t)4 * EE + 2 * (size_t)FFF * Ee];

// ---------------- helpers ----------------------------------------------------
__device__ __forceinline__ uint32_t smem_u32(const void* p) {
    uint32_t a;
    asm("{ .reg .u64 t; cvta.to.shared.u64 t, %1; cvt.u32.u64 %0, t; }" : "=r"(a) : "l"(p));
    return a;
}
#define CPA16(dst, src) asm volatile("cp.async.cg.shared.global [%0], [%1], 16;" :: "r"(dst), "l"(src))
#define CP_COMMIT()     asm volatile("cp.async.commit_group;" ::: "memory")
#define CP_WAIT(n)      asm volatile("cp.async.wait_group %0;" :: "n"(n) : "memory")

#define LDSM4(r0, r1, r2, r3, a)                                                \
    asm volatile("ldmatrix.sync.aligned.m8n8.x4.shared.b16 {%0,%1,%2,%3}, [%4];"\
        : "=r"(r0), "=r"(r1), "=r"(r2), "=r"(r3) : "r"(a))
#define LDSM4T(r0, r1, r2, r3, a)                                               \
    asm volatile("ldmatrix.sync.aligned.m8n8.x4.trans.shared.b16 {%0,%1,%2,%3}, [%4];"\
        : "=r"(r0), "=r"(r1), "=r"(r2), "=r"(r3) : "r"(a))
#define MMA16816(d, a, b)                                                       \
    asm volatile("mma.sync.aligned.m16n8k16.row.col.f32.f16.f16.f32 "           \
        "{%0,%1,%2,%3}, {%4,%5,%6,%7}, {%8,%9}, {%0,%1,%2,%3};"                 \
        : "+f"((d)[0]), "+f"((d)[1]), "+f"((d)[2]), "+f"((d)[3])                \
        : "r"((a)[0]), "r"((a)[1]), "r"((a)[2]), "r"((a)[3]),                   \
          "r"((b)[0]), "r"((b)[1]))

// ---------------- fp32 -> fp16 rounding converter ------------------------------
__global__ void cvt_kernel(const float* __restrict__ src,
                           __half* __restrict__ hi, int n)
{
    int i = (blockIdx.x * 256 + threadIdx.x) * 4;
    if (i >= n) return;
    float4 v = *(const float4*)(src + i);
    *(__half2*)(hi + i)     = __floats2half2_rn(v.x, v.y);
    *(__half2*)(hi + i + 2) = __floats2half2_rn(v.z, v.w);
}

// ---------------- fp16 HMMA GEMM, BK=64, cp.async 3-stage ----------------------
// C = A * op(B), both fp16, explicit leading dims (lda/ldb/ldc in elements).
// NN=false: B [N,K] rows with stride ldb. NN=true: B [K,N] rows with stride ldb.
// EPI 0: fp32 C (+bias,res). EPI 1: fp16 C (+bias). RELU pre-round.
// causal: 1 = skip tiles above diagonal, 2 = clamp K at diagonal.
// For causal != 0, m-tiles are processed in reverse order (heavy rows first).
// stage: A [0,18432) rows 144B-stride; B [18432,36864) (NN: 272B-stride rows)
#define STAGE 36864
#define NSTG 3
#define HSMEM (STAGE * NSTG)

template<bool NN, int EPIPL, bool RELU>
__global__ void __launch_bounds__(256, 2) hgemm(
    const __half* __restrict__ Ah, const __half* __restrict__ Bh,
    const float* __restrict__ bias, const float* __restrict__ res,
    float* __restrict__ C, __half* __restrict__ Ch,
    int N, int K, int lda, int ldb, int ldc,
    size_t sA, size_t sB, size_t sC, int causal)
{
    int ytile = causal ? (gridDim.y - 1 - blockIdx.y) : blockIdx.y;
    int m0 = ytile * 128, n0 = blockIdx.x * 128;
    if (causal == 1 && n0 > m0) return;
    size_t zo = (size_t)blockIdx.z;
    Ah += zo * sA;
    Bh += zo * sB;
    if (EPIPL) Ch += zo * sC;
    else       C  += zo * sC;

    extern __shared__ char sm[];
    uint32_t sb = smem_u32(sm);
    int tid = threadIdx.x, lane = tid & 31, wid = tid >> 5;
    int wm = (wid & 3) * 32, wn = (wid >> 2) * 64;

    int kend = K;
    if (causal == 2) { int l = m0 + 128; kend = (l < K) ? l : K; }
    int nch = kend >> 6;

    float c[2][8][4];
    #pragma unroll
    for (int i = 0; i < 2; i++)
        #pragma unroll
        for (int j = 0; j < 8; j++)
            #pragma unroll
            for (int q = 0; q < 4; q++) c[i][j][q] = 0.f;

    // issue one chunk's loads straight into smem stage via cp.async
    auto issue = [&](int ch, int stg) {
        int k0 = ch << 6;
        uint32_t st = sb + (uint32_t)stg * STAGE;
        #pragma unroll
        for (int i = 0; i < 4; i++) {
            int id = tid + (i << 8);
            int row = id >> 3, c16 = id & 7;           // 128 rows x 8 chunks
            CPA16(st + row * 144 + (c16 << 4),
                  Ah + (size_t)(m0 + row) * lda + k0 + (c16 << 3));
            if (NN) {
                int rw = id >> 4, cc = id & 15;        // 64 k-rows x 16 chunks
                CPA16(st + 18432 + rw * 272 + (cc << 4),
                      Bh + (size_t)(k0 + rw) * ldb + n0 + (cc << 3));
            } else {
                CPA16(st + 18432 + row * 144 + (c16 << 4),
                      Bh + (size_t)(n0 + row) * ldb + k0 + (c16 << 3));
            }
        }
    };

    uint32_t aOff   = (uint32_t)((wm + (lane & 15)) * 144 + (lane >> 4) * 16);
    uint32_t bOffNT = (uint32_t)(18432 + (wn + (lane & 7) + ((lane >> 4) << 3)) * 144
                                 + ((lane >> 3) & 1) * 16);
    uint32_t bOffNN = (uint32_t)(18432 + ((lane & 7) + (((lane >> 3) & 1) << 3)) * 272
                                 + (wn + ((lane >> 4) << 3)) * 2);

    // prologue: 2 stages in flight
    issue(0, 0); CP_COMMIT();
    if (nch > 1) issue(1, 1);
    CP_COMMIT();

    int stg = 0;
    for (int ch = 0; ch < nch; ch++) {
        CP_WAIT(1);               // stage for chunk ch has landed
        __syncthreads();          // all warps done with the stage being refilled
        if (ch + 2 < nch) issue(ch + 2, (stg + 2 >= NSTG) ? stg + 2 - NSTG : stg + 2);
        CP_COMMIT();

        uint32_t base = sb + (uint32_t)stg * STAGE;
        #pragma unroll
        for (int ks = 0; ks < 4; ks++) {
            uint32_t ah[2][4], bh[8][2];
            #pragma unroll
            for (int mt = 0; mt < 2; mt++) {
                uint32_t ad = base + aOff + mt * 2304 + ks * 32;
                LDSM4(ah[mt][0], ah[mt][1], ah[mt][2], ah[mt][3], ad);
            }
            #pragma unroll
            for (int p = 0; p < 4; p++) {
                if (NN) {
                    uint32_t bd = base + bOffNN + ks * 4352 + p * 32;
                    LDSM4T(bh[2*p][0], bh[2*p][1], bh[2*p+1][0], bh[2*p+1][1], bd);
                } else {
                    uint32_t bd = base + bOffNT + p * 2304 + ks * 32;
                    LDSM4(bh[2*p][0], bh[2*p][1], bh[2*p+1][0], bh[2*p+1][1], bd);
                }
            }
            #pragma unroll
            for (int mt = 0; mt < 2; mt++)
                #pragma unroll
                for (int nt = 0; nt < 8; nt++)
                    MMA16816(c[mt][nt], ah[mt], bh[nt]);
        }
        stg = (stg + 1 >= NSTG) ? 0 : stg + 1;
    }

    // epilogue
    int g = lane >> 2, tg = lane & 3;
    #pragma unroll
    for (int mt = 0; mt < 2; mt++) {
        #pragma unroll
        for (int nt = 0; nt < 8; nt++) {
            int n = n0 + wn + nt * 8 + tg * 2;
            #pragma unroll
            for (int hr = 0; hr < 2; hr++) {
                int m = m0 + wm + mt * 16 + g + hr * 8;
                float v0 = c[mt][nt][hr * 2 + 0], v1 = c[mt][nt][hr * 2 + 1];
                if (bias) { v0 += __ldg(&bias[n]); v1 += __ldg(&bias[n + 1]); }
                if (RELU) { v0 = fmaxf(v0, 0.f); v1 = fmaxf(v1, 0.f); }
                if (EPIPL) {
                    *(__half2*)(Ch + (size_t)m * ldc + n) = __floats2half2_rn(v0, v1);
                } else {
                    if (res) {
                        float2 r = *(const float2*)(res + (size_t)m * ldc + n);
                        v0 += r.x; v1 += r.y;
                    }
                    *(float2*)(C + (size_t)m * ldc + n) = make_float2(v0, v1);
                }
            }
        }
    }
}

// ---------------- LayerNorm -> fp16 -------------------------------------------
__global__ void ln_kernel(const float* __restrict__ x,
                          const float* __restrict__ gamma,
                          const float* __restrict__ beta,
                          __half* __restrict__ oh)
{
    int row = blockIdx.x;
    const float* xr = x + (size_t)row * Ee;
    float s = 0.f, s2 = 0.f;
    for (int i = threadIdx.x; i < Ee; i += 256) {
        float v = xr[i]; s += v; s2 += v * v;
    }
    __shared__ float sh[64];
    #pragma unroll
    for (int off = 16; off; off >>= 1) {
        s  += __shfl_xor_sync(0xffffffffu, s,  off);
        s2 += __shfl_xor_sync(0xffffffffu, s2, off);
    }
    int w = threadIdx.x >> 5, lane = threadIdx.x & 31;
    if (lane == 0) { sh[w] = s; sh[32 + w] = s2; }
    __syncthreads();
    if (w == 0) {
        s  = (lane < 8) ? sh[lane] : 0.f;
        s2 = (lane < 8) ? sh[32 + lane] : 0.f;
        #pragma unroll
        for (int off = 4; off; off >>= 1) {
            s  += __shfl_xor_sync(0xffffffffu, s,  off);
            s2 += __shfl_xor_sync(0xffffffffu, s2, off);
        }
        if (lane == 0) { sh[0] = s; sh[1] = s2; }
    }
    __syncthreads();
    float mean = sh[0] * (1.f / Ee);
    float var  = sh[1] * (1.f / Ee) - mean * mean;
    float inv  = rsqrtf(var + 1e-5f);
    for (int i = threadIdx.x; i < Ee; i += 256) {
        float y = (xr[i] - mean) * inv * gamma[i] + beta[i];
        oh[(size_t)row * Ee + i] = __float2half_rn(y);
    }
}

// ---------------- causal softmax -> fp16 ---------------------------------------
__global__ void softmax_kernel(const float* __restrict__ S, __half* __restrict__ ph)
{
    int t = blockIdx.x, b = blockIdx.y;
    const float* row = S + ((size_t)b * Tt + t) * Tt;
    __half* prh = ph + ((size_t)b * Tt + t) * Tt;
    int n = t + 1;
    const float scale = 0.0220970869120796101f;  // 1/sqrt(2048)
    __shared__ float sh[32];
    int w = threadIdx.x >> 5, lane = threadIdx.x & 31;

    float mx = -3.4e38f;
    for (int i = threadIdx.x; i < n; i += 256) mx = fmaxf(mx, row[i]);
    #pragma unroll
    for (int off = 16; off; off >>= 1) mx = fmaxf(mx, __shfl_xor_sync(0xffffffffu, mx, off));
    if (lane == 0) sh[w] = mx;
    __syncthreads();
    if (w == 0) {
        mx = (lane < 8) ? sh[lane] : -3.4e38f;
        #pragma unroll
        for (int off = 4; off; off >>= 1) mx = fmaxf(mx, __shfl_xor_sync(0xffffffffu, mx, off));
        if (lane == 0) sh[0] = mx;
    }
    __syncthreads();
    mx = sh[0];
    __syncthreads();

    float sum = 0.f;
    for (int i = threadIdx.x; i < n; i += 256) sum += __expf((row[i] - mx) * scale);
    #pragma unroll
    for (int off = 16; off; off >>= 1) sum += __shfl_xor_sync(0xffffffffu, sum, off);
    if (lane == 0) sh[w] = sum;
    __syncthreads();
    if (w == 0) {
        sum = (lane < 8) ? sh[lane] : 0.f;
        #pragma unroll
        for (int off = 4; off; off >>= 1) sum += __shfl_xor_sync(0xffffffffu, sum, off);
        if (lane == 0) sh[0] = sum;
    }
    __syncthreads();
    float inv = 1.f / sh[0];
    for (int i = threadIdx.x; i < Tt; i += 256) {
        float p = (i < n) ? __expf((row[i] - mx) * scale) * inv : 0.f;
        prh[i] = __float2half_rn(p);
    }
}

// ---------------- launch -------------------------------------------------------
extern "C" void kernel_launch(void* const* d_in, const int* in_sizes, int n_in,
                              void* d_out, int out_size)
{
    const float* x      = (const float*)d_in[0];
    const float* gamma1 = (const float*)d_in[1];
    const float* beta1  = (const float*)d_in[2];
    const float* Wq     = (const float*)d_in[3];
    const float* Wk     = (const float*)d_in[4];
    const float* Wv     = (const float*)d_in[5];
    const float* Wo     = (const float*)d_in[6];
    const float* bo     = (const float*)d_in[7];
    const float* gamma2 = (const float*)d_in[8];
    const float* beta2  = (const float*)d_in[9];
    const float* W1     = (const float*)d_in[10];
    const float* b1     = (const float*)d_in[11];
    const float* W2     = (const float*)d_in[12];
    const float* b2     = (const float*)d_in[13];
    float* out = (float*)d_out;

    float *s, *x1;
    __half *hh, *qkv, *ph, *ath, *ffh, *wh;
    cudaGetSymbolAddress((void**)&s,   g_s);
    cudaGetSymbolAddress((void**)&x1,  g_x1);
    cudaGetSymbolAddress((void**)&hh,  g_hh);
    cudaGetSymbolAddress((void**)&qkv, g_qkv);
    cudaGetSymbolAddress((void**)&ph,  g_ph);
    cudaGetSymbolAddress((void**)&ath, g_ath);
    cudaGetSymbolAddress((void**)&ffh, g_ffh);
    cudaGetSymbolAddress((void**)&wh,  g_wh);

    cudaFuncSetAttribute(hgemm<false, 0, false>, cudaFuncAttributeMaxDynamicSharedMemorySize, HSMEM);
    cudaFuncSetAttribute(hgemm<false, 1, false>, cudaFuncAttributeMaxDynamicSharedMemorySize, HSMEM);
    cudaFuncSetAttribute(hgemm<false, 1, true>,  cudaFuncAttributeMaxDynamicSharedMemorySize, HSMEM);
    cudaFuncSetAttribute(hgemm<true,  1, false>, cudaFuncAttributeMaxDynamicSharedMemorySize, HSMEM);

    const size_t oW1 = (size_t)4 * EE, oW2 = (size_t)4 * EE + (size_t)FFF * Ee;

    // 0) weight rounding (fp32 -> fp16); wh[0..3EE) is the fused QKV matrix [3E, E]
    cvt_kernel<<<EE / 1024, 256>>>(Wq, wh,          EE);
    cvt_kernel<<<EE / 1024, 256>>>(Wk, wh + EE,     EE);
    cvt_kernel<<<EE / 1024, 256>>>(Wv, wh + 2 * EE, EE);
    cvt_kernel<<<EE / 1024, 256>>>(Wo, wh + 3 * EE, EE);
    cvt_kernel<<<FFF * Ee / 1024, 256>>>(W1, wh + oW1, FFF * Ee);
    cvt_kernel<<<FFF * Ee / 1024, 256>>>(W2, wh + oW2, FFF * Ee);

    // 1) LN1 -> fp16
    ln_kernel<<<MR, 256>>>(x, gamma1, beta1, hh);

    // 2) fused QKV projection: [MR, E] x [3E, E]^T -> qkv [MR, 6144]
    dim3 gQKV(QKVN / 128, MR / 128, 1);
    hgemm<false, 1, false><<<gQKV, 256, HSMEM>>>(hh, wh, nullptr, nullptr, nullptr, qkv,
                                                 QKVN, Ee, Ee, Ee, QKVN, 0, 0, 0, 0);

    // 3) S = q k^T (fp32 out, causal tile skip, reversed y for balance)
    dim3 gQK(Tt / 128, Tt / 128, Bb);
    hgemm<false, 0, false><<<gQK, 256, HSMEM>>>(qkv, qkv + 2048, nullptr, nullptr, s, nullptr,
                                                Tt, Ee, QKVN, QKVN, Tt,
                                                (size_t)Tt * QKVN, (size_t)Tt * QKVN, (size_t)Tt * Tt, 1);

    // 4) causal softmax -> fp16 probs
    softmax_kernel<<<dim3(Tt, Bb), 256>>>(s, ph);

    // 5) attn = P @ V (NN, K clamped at diagonal, reversed y) -> fp16
    dim3 gPV(Ee / 128, Tt / 128, Bb);
    hgemm<true, 1, false><<<gPV, 256, HSMEM>>>(ph, qkv + 4096, nullptr, nullptr, nullptr, ath,
                                               Ee, Tt, Tt, QKVN, Ee,
                                               (size_t)Tt * Tt, (size_t)Tt * QKVN, (size_t)Tt * Ee, 2);

    // 6) x1 = attn Wo^T + bo + x (fp32)
    dim3 gProj(Ee / 128, MR / 128, 1);
    hgemm<false, 0, false><<<gProj, 256, HSMEM>>>(ath, wh + 3 * EE, bo, x, x1, nullptr,
                                                  Ee, Ee, Ee, Ee, Ee, 0, 0, 0, 0);

    // 7) LN2 -> fp16
    ln_kernel<<<MR, 256>>>(x1, gamma2, beta2, hh);

    // 8) ff = relu(h W1^T + b1) -> fp16
    dim3 gFF1(FFF / 128, MR / 128, 1);
    hgemm<false, 1, true><<<gFF1, 256, HSMEM>>>(hh, wh + oW1, b1, nullptr, nullptr, ffh,
                                                FFF, Ee, Ee, Ee, FFF, 0, 0, 0, 0);

    // 9) out = ff W2^T + b2 + x1 (fp32)
    dim3 gFF2(Ee / 128, MR / 128, 1);
    hgemm<false, 0, false><<<gFF2, 256, HSMEM>>>(ffh, wh + oW2, b2, x1, out, nullptr,
                                                 Ee, FFF, FFF, FFF, Ee, 0, 0, 0, 0);
}

// round 16
// speedup vs baseline: 1.0835x; 1.0025x over previous
#include <cuda_runtime.h>
#include <cuda_fp16.h>
#include <cstdint>
#include <math.h>

#define Bb 8
#define Tt 2048
#define Ee 2048
#define FFF 8192
#define MR (Bb * Tt)
#define EE (Ee * Ee)
#define QKVN (3 * Ee)   // 6144

// ---------------- scratch ---------------------------------------------------
__device__ float  g_x1 [(size_t)MR * Ee];
__device__ __half g_hh [(size_t)MR * Ee];
__device__ __half g_qkv[(size_t)MR * QKVN];
__device__ __half g_ph [(size_t)Bb * Tt * Tt];   // raw logits, then probs (in place)
__device__ __half g_ath[(size_t)MR * Ee];
__device__ __half g_ffh[(size_t)MR * FFF];
__device__ __half g_wh [(size_t)4 * EE + 2 * (size_t)FFF * Ee];

// ---------------- helpers ----------------------------------------------------
__device__ __forceinline__ uint32_t smem_u32(const void* p) {
    uint32_t a;
    asm("{ .reg .u64 t; cvta.to.shared.u64 t, %1; cvt.u32.u64 %0, t; }" : "=r"(a) : "l"(p));
    return a;
}
#define CPA16(dst, src) asm volatile("cp.async.cg.shared.global [%0], [%1], 16;" :: "r"(dst), "l"(src))
#define CP_COMMIT()     asm volatile("cp.async.commit_group;" ::: "memory")
#define CP_WAIT(n)      asm volatile("cp.async.wait_group %0;" :: "n"(n) : "memory")

#define LDSM4(r0, r1, r2, r3, a)                                                \
    asm volatile("ldmatrix.sync.aligned.m8n8.x4.shared.b16 {%0,%1,%2,%3}, [%4];"\
        : "=r"(r0), "=r"(r1), "=r"(r2), "=r"(r3) : "r"(a))
#define LDSM4T(r0, r1, r2, r3, a)                                               \
    asm volatile("ldmatrix.sync.aligned.m8n8.x4.trans.shared.b16 {%0,%1,%2,%3}, [%4];"\
        : "=r"(r0), "=r"(r1), "=r"(r2), "=r"(r3) : "r"(a))
#define MMA16816(d, a, b)                                                       \
    asm volatile("mma.sync.aligned.m16n8k16.row.col.f32.f16.f16.f32 "           \
        "{%0,%1,%2,%3}, {%4,%5,%6,%7}, {%8,%9}, {%0,%1,%2,%3};"                 \
        : "+f"((d)[0]), "+f"((d)[1]), "+f"((d)[2]), "+f"((d)[3])                \
        : "r"((a)[0]), "r"((a)[1]), "r"((a)[2]), "r"((a)[3]),                   \
          "r"((b)[0]), "r"((b)[1]))

// ---------------- fp32 -> fp16 rounding converter ------------------------------
__global__ void cvt_kernel(const float* __restrict__ src,
                           __half* __restrict__ hi, int n)
{
    int i = (blockIdx.x * 256 + threadIdx.x) * 4;
    if (i >= n) return;
    float4 v = *(const float4*)(src + i);
    *(__half2*)(hi + i)     = __floats2half2_rn(v.x, v.y);
    *(__half2*)(hi + i + 2) = __floats2half2_rn(v.z, v.w);
}

// ---------------- fp16 HMMA GEMM, BK=64, cp.async 3-stage ----------------------
// C = A * op(B), both fp16, explicit leading dims (lda/ldb/ldc in elements).
// NN=false: B [N,K] rows with stride ldb. NN=true: B [K,N] rows with stride ldb.
// EPI 0: fp32 C (+bias,res). EPI 1: fp16 C (+bias). RELU pre-round.
// causal: 1 = skip tiles above diagonal, 2 = clamp K at diagonal.
// For causal != 0, m-tiles are processed in reverse order (heavy rows first).
// stage: A [0,18432) rows 144B-stride; B [18432,36864) (NN: 272B-stride rows)
#define STAGE 36864
#define NSTG 3
#define HSMEM (STAGE * NSTG)

template<bool NN, int EPIPL, bool RELU>
__global__ void __launch_bounds__(256, 2) hgemm(
    const __half* __restrict__ Ah, const __half* __restrict__ Bh,
    const float* __restrict__ bias, const float* __restrict__ res,
    float* __restrict__ C, __half* __restrict__ Ch,
    int N, int K, int lda, int ldb, int ldc,
    size_t sA, size_t sB, size_t sC, int causal)
{
    int ytile = causal ? (gridDim.y - 1 - blockIdx.y) : blockIdx.y;
    int m0 = ytile * 128, n0 = blockIdx.x * 128;
    if (causal == 1 && n0 > m0) return;
    size_t zo = (size_t)blockIdx.z;
    Ah += zo * sA;
    Bh += zo * sB;
    if (EPIPL) Ch += zo * sC;
    else       C  += zo * sC;

    extern __shared__ char sm[];
    uint32_t sb = smem_u32(sm);
    int tid = threadIdx.x, lane = tid & 31, wid = tid >> 5;
    int wm = (wid & 3) * 32, wn = (wid >> 2) * 64;

    int kend = K;
    if (causal == 2) { int l = m0 + 128; kend = (l < K) ? l : K; }
    int nch = kend >> 6;

    float c[2][8][4];
    #pragma unroll
    for (int i = 0; i < 2; i++)
        #pragma unroll
        for (int j = 0; j < 8; j++)
            #pragma unroll
            for (int q = 0; q < 4; q++) c[i][j][q] = 0.f;

    // issue one chunk's loads straight into smem stage via cp.async
    auto issue = [&](int ch, int stg) {
        int k0 = ch << 6;
        uint32_t st = sb + (uint32_t)stg * STAGE;
        #pragma unroll
        for (int i = 0; i < 4; i++) {
            int id = tid + (i << 8);
            int row = id >> 3, c16 = id & 7;           // 128 rows x 8 chunks
            CPA16(st + row * 144 + (c16 << 4),
                  Ah + (size_t)(m0 + row) * lda + k0 + (c16 << 3));
            if (NN) {
                int rw = id >> 4, cc = id & 15;        // 64 k-rows x 16 chunks
                CPA16(st + 18432 + rw * 272 + (cc << 4),
                      Bh + (size_t)(k0 + rw) * ldb + n0 + (cc << 3));
            } else {
                CPA16(st + 18432 + row * 144 + (c16 << 4),
                      Bh + (size_t)(n0 + row) * ldb + k0 + (c16 << 3));
            }
        }
    };

    uint32_t aOff   = (uint32_t)((wm + (lane & 15)) * 144 + (lane >> 4) * 16);
    uint32_t bOffNT = (uint32_t)(18432 + (wn + (lane & 7) + ((lane >> 4) << 3)) * 144
                                 + ((lane >> 3) & 1) * 16);
    uint32_t bOffNN = (uint32_t)(18432 + ((lane & 7) + (((lane >> 3) & 1) << 3)) * 272
                                 + (wn + ((lane >> 4) << 3)) * 2);

    // prologue: 2 stages in flight
    issue(0, 0); CP_COMMIT();
    if (nch > 1) issue(1, 1);
    CP_COMMIT();

    int stg = 0;
    for (int ch = 0; ch < nch; ch++) {
        CP_WAIT(1);               // stage for chunk ch has landed
        __syncthreads();          // all warps done with the stage being refilled
        if (ch + 2 < nch) issue(ch + 2, (stg + 2 >= NSTG) ? stg + 2 - NSTG : stg + 2);
        CP_COMMIT();

        uint32_t base = sb + (uint32_t)stg * STAGE;
        #pragma unroll
        for (int ks = 0; ks < 4; ks++) {
            uint32_t ah[2][4], bh[8][2];
            #pragma unroll
            for (int mt = 0; mt < 2; mt++) {
                uint32_t ad = base + aOff + mt * 2304 + ks * 32;
                LDSM4(ah[mt][0], ah[mt][1], ah[mt][2], ah[mt][3], ad);
            }
            #pragma unroll
            for (int p = 0; p < 4; p++) {
                if (NN) {
                    uint32_t bd = base + bOffNN + ks * 4352 + p * 32;
                    LDSM4T(bh[2*p][0], bh[2*p][1], bh[2*p+1][0], bh[2*p+1][1], bd);
                } else {
                    uint32_t bd = base + bOffNT + p * 2304 + ks * 32;
                    LDSM4(bh[2*p][0], bh[2*p][1], bh[2*p+1][0], bh[2*p+1][1], bd);
                }
            }
            #pragma unroll
            for (int mt = 0; mt < 2; mt++)
                #pragma unroll
                for (int nt = 0; nt < 8; nt++)
                    MMA16816(c[mt][nt], ah[mt], bh[nt]);
        }
        stg = (stg + 1 >= NSTG) ? 0 : stg + 1;
    }

    // epilogue
    int g = lane >> 2, tg = lane & 3;
    #pragma unroll
    for (int mt = 0; mt < 2; mt++) {
        #pragma unroll
        for (int nt = 0; nt < 8; nt++) {
            int n = n0 + wn + nt * 8 + tg * 2;
            #pragma unroll
            for (int hr = 0; hr < 2; hr++) {
                int m = m0 + wm + mt * 16 + g + hr * 8;
                float v0 = c[mt][nt][hr * 2 + 0], v1 = c[mt][nt][hr * 2 + 1];
                if (bias) { v0 += __ldg(&bias[n]); v1 += __ldg(&bias[n + 1]); }
                if (RELU) { v0 = fmaxf(v0, 0.f); v1 = fmaxf(v1, 0.f); }
                if (EPIPL) {
                    *(__half2*)(Ch + (size_t)m * ldc + n) = __floats2half2_rn(v0, v1);
                } else {
                    if (res) {
                        float2 r = *(const float2*)(res + (size_t)m * ldc + n);
                        v0 += r.x; v1 += r.y;
                    }
                    *(float2*)(C + (size_t)m * ldc + n) = make_float2(v0, v1);
                }
            }
        }
    }
}

// ---------------- LayerNorm -> fp16 -------------------------------------------
__global__ void ln_kernel(const float* __restrict__ x,
                          const float* __restrict__ gamma,
                          const float* __restrict__ beta,
                          __half* __restrict__ oh)
{
    int row = blockIdx.x;
    const float* xr = x + (size_t)row * Ee;
    float s = 0.f, s2 = 0.f;
    for (int i = threadIdx.x; i < Ee; i += 256) {
        float v = xr[i]; s += v; s2 += v * v;
    }
    __shared__ float sh[64];
    #pragma unroll
    for (int off = 16; off; off >>= 1) {
        s  += __shfl_xor_sync(0xffffffffu, s,  off);
        s2 += __shfl_xor_sync(0xffffffffu, s2, off);
    }
    int w = threadIdx.x >> 5, lane = threadIdx.x & 31;
    if (lane == 0) { sh[w] = s; sh[32 + w] = s2; }
    __syncthreads();
    if (w == 0) {
        s  = (lane < 8) ? sh[lane] : 0.f;
        s2 = (lane < 8) ? sh[32 + lane] : 0.f;
        #pragma unroll
        for (int off = 4; off; off >>= 1) {
            s  += __shfl_xor_sync(0xffffffffu, s,  off);
            s2 += __shfl_xor_sync(0xffffffffu, s2, off);
        }
        if (lane == 0) { sh[0] = s; sh[1] = s2; }
    }
    __syncthreads();
    float mean = sh[0] * (1.f / Ee);
    float var  = sh[1] * (1.f / Ee) - mean * mean;
    float inv  = rsqrtf(var + 1e-5f);
    for (int i = threadIdx.x; i < Ee; i += 256) {
        float y = (xr[i] - mean) * inv * gamma[i] + beta[i];
        oh[(size_t)row * Ee + i] = __float2half_rn(y);
    }
}

// ---------------- causal softmax, in place on fp16 logits ----------------------
// One block per (t, b) row. Stages the active prefix in smem: ONE gmem read pass.
__global__ void softmax_kernel(__half* __restrict__ P)
{
    int t = blockIdx.x, b = blockIdx.y;
    __half* row = P + ((size_t)b * Tt + t) * Tt;
    int n = t + 1;
    const float scale = 0.0220970869120796101f;  // 1/sqrt(2048)
    __shared__ float buf[Tt];                    // 8 KB
    __shared__ float sh[32];
    int w = threadIdx.x >> 5, lane = threadIdx.x & 31;

    for (int i = threadIdx.x; i < n; i += 256) buf[i] = __half2float(row[i]);
    __syncthreads();

    float mx = -3.4e38f;
    for (int i = threadIdx.x; i < n; i += 256) mx = fmaxf(mx, buf[i]);
    #pragma unroll
    for (int off = 16; off; off >>= 1) mx = fmaxf(mx, __shfl_xor_sync(0xffffffffu, mx, off));
    if (lane == 0) sh[w] = mx;
    __syncthreads();
    if (w == 0) {
        mx = (lane < 8) ? sh[lane] : -3.4e38f;
        #pragma unroll
        for (int off = 4; off; off >>= 1) mx = fmaxf(mx, __shfl_xor_sync(0xffffffffu, mx, off));
        if (lane == 0) sh[0] = mx;
    }
    __syncthreads();
    mx = sh[0];
    __syncthreads();

    float sum = 0.f;
    for (int i = threadIdx.x; i < n; i += 256) sum += __expf((buf[i] - mx) * scale);
    #pragma unroll
    for (int off = 16; off; off >>= 1) sum += __shfl_xor_sync(0xffffffffu, sum, off);
    if (lane == 0) sh[w] = sum;
    __syncthreads();
    if (w == 0) {
        sum = (lane < 8) ? sh[lane] : 0.f;
        #pragma unroll
        for (int off = 4; off; off >>= 1) sum += __shfl_xor_sync(0xffffffffu, sum, off);
        if (lane == 0) sh[0] = sum;
    }
    __syncthreads();
    float inv = 1.f / sh[0];

    for (int i = threadIdx.x; i < Tt; i += 256) {
        float p = (i < n) ? __expf((buf[i] - mx) * scale) * inv : 0.f;
        row[i] = __float2half_rn(p);
    }
}

// ---------------- launch -------------------------------------------------------
extern "C" void kernel_launch(void* const* d_in, const int* in_sizes, int n_in,
                              void* d_out, int out_size)
{
    const float* x      = (const float*)d_in[0];
    const float* gamma1 = (const float*)d_in[1];
    const float* beta1  = (const float*)d_in[2];
    const float* Wq     = (const float*)d_in[3];
    const float* Wk     = (const float*)d_in[4];
    const float* Wv     = (const float*)d_in[5];
    const float* Wo     = (const float*)d_in[6];
    const float* bo     = (const float*)d_in[7];
    const float* gamma2 = (const float*)d_in[8];
    const float* beta2  = (const float*)d_in[9];
    const float* W1     = (const float*)d_in[10];
    const float* b1     = (const float*)d_in[11];
    const float* W2     = (const float*)d_in[12];
    const float* b2     = (const float*)d_in[13];
    float* out = (float*)d_out;

    float *x1;
    __half *hh, *qkv, *ph, *ath, *ffh, *wh;
    cudaGetSymbolAddress((void**)&x1,  g_x1);
    cudaGetSymbolAddress((void**)&hh,  g_hh);
    cudaGetSymbolAddress((void**)&qkv, g_qkv);
    cudaGetSymbolAddress((void**)&ph,  g_ph);
    cudaGetSymbolAddress((void**)&ath, g_ath);
    cudaGetSymbolAddress((void**)&ffh, g_ffh);
    cudaGetSymbolAddress((void**)&wh,  g_wh);

    cudaFuncSetAttribute(hgemm<false, 0, false>, cudaFuncAttributeMaxDynamicSharedMemorySize, HSMEM);
    cudaFuncSetAttribute(hgemm<false, 1, false>, cudaFuncAttributeMaxDynamicSharedMemorySize, HSMEM);
    cudaFuncSetAttribute(hgemm<false, 1, true>,  cudaFuncAttributeMaxDynamicSharedMemorySize, HSMEM);
    cudaFuncSetAttribute(hgemm<true,  1, false>, cudaFuncAttributeMaxDynamicSharedMemorySize, HSMEM);

    const size_t oW1 = (size_t)4 * EE, oW2 = (size_t)4 * EE + (size_t)FFF * Ee;

    // 0) weight rounding (fp32 -> fp16); wh[0..3EE) is the fused QKV matrix [3E, E]
    cvt_kernel<<<EE / 1024, 256>>>(Wq, wh,          EE);
    cvt_kernel<<<EE / 1024, 256>>>(Wk, wh + EE,     EE);
    cvt_kernel<<<EE / 1024, 256>>>(Wv, wh + 2 * EE, EE);
    cvt_kernel<<<EE / 1024, 256>>>(Wo, wh + 3 * EE, EE);
    cvt_kernel<<<FFF * Ee / 1024, 256>>>(W1, wh + oW1, FFF * Ee);
    cvt_kernel<<<FFF * Ee / 1024, 256>>>(W2, wh + oW2, FFF * Ee);

    // 1) LN1 -> fp16
    ln_kernel<<<MR, 256>>>(x, gamma1, beta1, hh);

    // 2) fused QKV projection: [MR, E] x [3E, E]^T -> qkv [MR, 6144]
    dim3 gQKV(QKVN / 128, MR / 128, 1);
    hgemm<false, 1, false><<<gQKV, 256, HSMEM>>>(hh, wh, nullptr, nullptr, nullptr, qkv,
                                                 QKVN, Ee, Ee, Ee, QKVN, 0, 0, 0, 0);

    // 3) raw logits = q k^T -> fp16 ph (causal tile skip, reversed y)
    dim3 gQK(Tt / 128, Tt / 128, Bb);
    hgemm<false, 1, false><<<gQK, 256, HSMEM>>>(qkv, qkv + 2048, nullptr, nullptr, nullptr, ph,
                                                Tt, Ee, QKVN, QKVN, Tt,
                                                (size_t)Tt * QKVN, (size_t)Tt * QKVN, (size_t)Tt * Tt, 1);

    // 4) causal softmax in place on ph (single gmem read pass via smem staging)
    softmax_kernel<<<dim3(Tt, Bb), 256>>>(ph);

    // 5) attn = P @ V (NN, K clamped at diagonal, reversed y) -> fp16
    dim3 gPV(Ee / 128, Tt / 128, Bb);
    hgemm<true, 1, false><<<gPV, 256, HSMEM>>>(ph, qkv + 4096, nullptr, nullptr, nullptr, ath,
                                               Ee, Tt, Tt, QKVN, Ee,
                                               (size_t)Tt * Tt, (size_t)Tt * QKVN, (size_t)Tt * Ee, 2);

    // 6) x1 = attn Wo^T + bo + x (fp32)
    dim3 gProj(Ee / 128, MR / 128, 1);
    hgemm<false, 0, false><<<gProj, 256, HSMEM>>>(ath, wh + 3 * EE, bo, x, x1, nullptr,
                                                  Ee, Ee, Ee, Ee, Ee, 0, 0, 0, 0);

    // 7) LN2 -> fp16
    ln_kernel<<<MR, 256>>>(x1, gamma2, beta2, hh);

    // 8) ff = relu(h W1^T + b1) -> fp16
    dim3 gFF1(FFF / 128, MR / 128, 1);
    hgemm<false, 1, true><<<gFF1, 256, HSMEM>>>(hh, wh + oW1, b1, nullptr, nullptr, ffh,
                                                FFF, Ee, Ee, Ee, FFF, 0, 0, 0, 0);

    // 9) out = ff W2^T + b2 + x1 (fp32)
    dim3 gFF2(Ee / 128, MR / 128, 1);
    hgemm<false, 0, false><<<gFF2, 256, HSMEM>>>(ffh, wh + oW2, b2, x1, out, nullptr,
                                                 Ee, FFF, FFF, FFF, Ee, 0, 0, 0, 0);
}

// round 17
// speedup vs baseline: 1.0852x; 1.0016x over previous
#include <cuda_runtime.h>
#include <cuda_fp16.h>
#include <cstdint>
#include <math.h>

#define Bb 8
#define Tt 2048
#define Ee 2048
#define FFF 8192
#define MR (Bb * Tt)
#define EE (Ee * Ee)
#define QKVN (3 * Ee)   // 6144

// ---------------- scratch ---------------------------------------------------
__device__ float  g_x1 [(size_t)MR * Ee];
__device__ __half g_hh [(size_t)MR * Ee];
__device__ __half g_qkv[(size_t)MR * QKVN];
__device__ __half g_ph [(size_t)Bb * Tt * Tt];   // raw logits, then probs (in place)
__device__ __half g_ath[(size_t)MR * Ee];
__device__ __half g_ffh[(size_t)MR * FFF];
__device__ __half g_wh [(size_t)4 * EE + 2 * (size_t)FFF * Ee];

// ---------------- helpers ----------------------------------------------------
__device__ __forceinline__ uint32_t smem_u32(const void* p) {
    uint32_t a;
    asm("{ .reg .u64 t; cvta.to.shared.u64 t, %1; cvt.u32.u64 %0, t; }" : "=r"(a) : "l"(p));
    return a;
}
#define CPA16(dst, src) asm volatile("cp.async.cg.shared.global [%0], [%1], 16;" :: "r"(dst), "l"(src))
#define CP_COMMIT()     asm volatile("cp.async.commit_group;" ::: "memory")
#define CP_WAIT(n)      asm volatile("cp.async.wait_group %0;" :: "n"(n) : "memory")

#define LDSM4(r0, r1, r2, r3, a)                                                \
    asm volatile("ldmatrix.sync.aligned.m8n8.x4.shared.b16 {%0,%1,%2,%3}, [%4];"\
        : "=r"(r0), "=r"(r1), "=r"(r2), "=r"(r3) : "r"(a))
#define LDSM4T(r0, r1, r2, r3, a)                                               \
    asm volatile("ldmatrix.sync.aligned.m8n8.x4.trans.shared.b16 {%0,%1,%2,%3}, [%4];"\
        : "=r"(r0), "=r"(r1), "=r"(r2), "=r"(r3) : "r"(a))
#define MMA16816(d, a, b)                                                       \
    asm volatile("mma.sync.aligned.m16n8k16.row.col.f32.f16.f16.f32 "           \
        "{%0,%1,%2,%3}, {%4,%5,%6,%7}, {%8,%9}, {%0,%1,%2,%3};"                 \
        : "+f"((d)[0]), "+f"((d)[1]), "+f"((d)[2]), "+f"((d)[3])                \
        : "r"((a)[0]), "r"((a)[1]), "r"((a)[2]), "r"((a)[3]),                   \
          "r"((b)[0]), "r"((b)[1]))

// ---------------- fused fp32 -> fp16 weight converter --------------------------
// Six segments converted in ONE launch; seg boundaries in units of 1024 floats.
__global__ void cvt6_kernel(const float* __restrict__ s0, const float* __restrict__ s1,
                            const float* __restrict__ s2, const float* __restrict__ s3,
                            const float* __restrict__ s4, const float* __restrict__ s5,
                            __half* __restrict__ dst)
{
    // segment sizes (elements): 4x EE, 2x FFF*Ee
    const size_t szA = (size_t)EE;            // 4 of these
    const size_t szB = (size_t)FFF * Ee;      // 2 of these
    size_t i = ((size_t)blockIdx.x * 256 + threadIdx.x) * 4;
    const float* src;
    size_t off;
    if (i < 4 * szA) {
        int seg = (int)(i / szA);
        off = i - (size_t)seg * szA;
        src = seg == 0 ? s0 : seg == 1 ? s1 : seg == 2 ? s2 : s3;
    } else {
        size_t j = i - 4 * szA;
        if (j < szB) { src = s4; off = j; }
        else         { src = s5; off = j - szB; }
    }
    float4 v = *(const float4*)(src + off);
    *(__half2*)(dst + i)     = __floats2half2_rn(v.x, v.y);
    *(__half2*)(dst + i + 2) = __floats2half2_rn(v.z, v.w);
}

// ---------------- fp16 HMMA GEMM, BK=64, cp.async 3-stage ----------------------
// C = A * op(B), both fp16, explicit leading dims (lda/ldb/ldc in elements).
// NN=false: B [N,K] rows with stride ldb. NN=true: B [K,N] rows with stride ldb.
// EPI 0: fp32 C (+bias,res). EPI 1: fp16 C (+bias). RELU pre-round.
// causal: 0 none; 2 = clamp K at diagonal (reversed y for balance);
//         3 = packed lower-triangular grid (blockIdx.x = tri index, grid.y==1).
// stage: A [0,18432) rows 144B-stride; B [18432,36864) (NN: 272B-stride rows)
#define STAGE 36864
#define NSTG 3
#define HSMEM (STAGE * NSTG)

template<bool NN, int EPIPL, bool RELU>
__global__ void __launch_bounds__(256, 2) hgemm(
    const __half* __restrict__ Ah, const __half* __restrict__ Bh,
    const float* __restrict__ bias, const float* __restrict__ res,
    float* __restrict__ C, __half* __restrict__ Ch,
    int N, int K, int lda, int ldb, int ldc,
    size_t sA, size_t sB, size_t sC, int causal)
{
    int m0, n0;
    if (causal == 3) {
        // packed lower triangle: idx -> (mt, nt), nt <= mt
        int idx = blockIdx.x;
        int mt = (int)((sqrtf(8.f * (float)idx + 1.f) - 1.f) * 0.5f);
        while ((mt + 1) * (mt + 2) / 2 <= idx) mt++;
        while (mt * (mt + 1) / 2 > idx) mt--;
        int nt = idx - mt * (mt + 1) / 2;
        m0 = mt * 128; n0 = nt * 128;
    } else {
        int ytile = causal ? (gridDim.y - 1 - blockIdx.y) : blockIdx.y;
        m0 = ytile * 128; n0 = blockIdx.x * 128;
    }
    size_t zo = (size_t)blockIdx.z;
    Ah += zo * sA;
    Bh += zo * sB;
    if (EPIPL) Ch += zo * sC;
    else       C  += zo * sC;

    extern __shared__ char sm[];
    uint32_t sb = smem_u32(sm);
    int tid = threadIdx.x, lane = tid & 31, wid = tid >> 5;
    int wm = (wid & 3) * 32, wn = (wid >> 2) * 64;

    int kend = K;
    if (causal == 2) { int l = m0 + 128; kend = (l < K) ? l : K; }
    int nch = kend >> 6;

    float c[2][8][4];
    #pragma unroll
    for (int i = 0; i < 2; i++)
        #pragma unroll
        for (int j = 0; j < 8; j++)
            #pragma unroll
            for (int q = 0; q < 4; q++) c[i][j][q] = 0.f;

    // issue one chunk's loads straight into smem stage via cp.async
    auto issue = [&](int ch, int stg) {
        int k0 = ch << 6;
        uint32_t st = sb + (uint32_t)stg * STAGE;
        #pragma unroll
        for (int i = 0; i < 4; i++) {
            int id = tid + (i << 8);
            int row = id >> 3, c16 = id & 7;           // 128 rows x 8 chunks
            CPA16(st + row * 144 + (c16 << 4),
                  Ah + (size_t)(m0 + row) * lda + k0 + (c16 << 3));
            if (NN) {
                int rw = id >> 4, cc = id & 15;        // 64 k-rows x 16 chunks
                CPA16(st + 18432 + rw * 272 + (cc << 4),
                      Bh + (size_t)(k0 + rw) * ldb + n0 + (cc << 3));
            } else {
                CPA16(st + 18432 + row * 144 + (c16 << 4),
                      Bh + (size_t)(n0 + row) * ldb + k0 + (c16 << 3));
            }
        }
    };

    uint32_t aOff   = (uint32_t)((wm + (lane & 15)) * 144 + (lane >> 4) * 16);
    uint32_t bOffNT = (uint32_t)(18432 + (wn + (lane & 7) + ((lane >> 4) << 3)) * 144
                                 + ((lane >> 3) & 1) * 16);
    uint32_t bOffNN = (uint32_t)(18432 + ((lane & 7) + (((lane >> 3) & 1) << 3)) * 272
                                 + (wn + ((lane >> 4) << 3)) * 2);

    // prologue: 2 stages in flight
    issue(0, 0); CP_COMMIT();
    if (nch > 1) issue(1, 1);
    CP_COMMIT();

    int stg = 0;
    for (int ch = 0; ch < nch; ch++) {
        CP_WAIT(1);               // stage for chunk ch has landed
        __syncthreads();          // all warps done with the stage being refilled
        if (ch + 2 < nch) issue(ch + 2, (stg + 2 >= NSTG) ? stg + 2 - NSTG : stg + 2);
        CP_COMMIT();

        uint32_t base = sb + (uint32_t)stg * STAGE;
        #pragma unroll
        for (int ks = 0; ks < 4; ks++) {
            uint32_t ah[2][4], bh[8][2];
            #pragma unroll
            for (int mt = 0; mt < 2; mt++) {
                uint32_t ad = base + aOff + mt * 2304 + ks * 32;
                LDSM4(ah[mt][0], ah[mt][1], ah[mt][2], ah[mt][3], ad);
            }
            #pragma unroll
            for (int p = 0; p < 4; p++) {
                if (NN) {
                    uint32_t bd = base + bOffNN + ks * 4352 + p * 32;
                    LDSM4T(bh[2*p][0], bh[2*p][1], bh[2*p+1][0], bh[2*p+1][1], bd);
                } else {
                    uint32_t bd = base + bOffNT + p * 2304 + ks * 32;
                    LDSM4(bh[2*p][0], bh[2*p][1], bh[2*p+1][0], bh[2*p+1][1], bd);
                }
            }
            #pragma unroll
            for (int mt = 0; mt < 2; mt++)
                #pragma unroll
                for (int nt = 0; nt < 8; nt++)
                    MMA16816(c[mt][nt], ah[mt], bh[nt]);
        }
        stg = (stg + 1 >= NSTG) ? 0 : stg + 1;
    }

    // epilogue
    int g = lane >> 2, tg = lane & 3;
    #pragma unroll
    for (int mt = 0; mt < 2; mt++) {
        #pragma unroll
        for (int nt = 0; nt < 8; nt++) {
            int n = n0 + wn + nt * 8 + tg * 2;
            #pragma unroll
            for (int hr = 0; hr < 2; hr++) {
                int m = m0 + wm + mt * 16 + g + hr * 8;
                float v0 = c[mt][nt][hr * 2 + 0], v1 = c[mt][nt][hr * 2 + 1];
                if (bias) { v0 += __ldg(&bias[n]); v1 += __ldg(&bias[n + 1]); }
                if (RELU) { v0 = fmaxf(v0, 0.f); v1 = fmaxf(v1, 0.f); }
                if (EPIPL) {
                    *(__half2*)(Ch + (size_t)m * ldc + n) = __floats2half2_rn(v0, v1);
                } else {
                    if (res) {
                        float2 r = *(const float2*)(res + (size_t)m * ldc + n);
                        v0 += r.x; v1 += r.y;
                    }
                    *(float2*)(C + (size_t)m * ldc + n) = make_float2(v0, v1);
                }
            }
        }
    }
}

// ---------------- LayerNorm -> fp16 -------------------------------------------
__global__ void ln_kernel(const float* __restrict__ x,
                          const float* __restrict__ gamma,
                          const float* __restrict__ beta,
                          __half* __restrict__ oh)
{
    int row = blockIdx.x;
    const float* xr = x + (size_t)row * Ee;
    float s = 0.f, s2 = 0.f;
    for (int i = threadIdx.x; i < Ee; i += 256) {
        float v = xr[i]; s += v; s2 += v * v;
    }
    __shared__ float sh[64];
    #pragma unroll
    for (int off = 16; off; off >>= 1) {
        s  += __shfl_xor_sync(0xffffffffu, s,  off);
        s2 += __shfl_xor_sync(0xffffffffu, s2, off);
    }
    int w = threadIdx.x >> 5, lane = threadIdx.x & 31;
    if (lane == 0) { sh[w] = s; sh[32 + w] = s2; }
    __syncthreads();
    if (w == 0) {
        s  = (lane < 8) ? sh[lane] : 0.f;
        s2 = (lane < 8) ? sh[32 + lane] : 0.f;
        #pragma unroll
        for (int off = 4; off; off >>= 1) {
            s  += __shfl_xor_sync(0xffffffffu, s,  off);
            s2 += __shfl_xor_sync(0xffffffffu, s2, off);
        }
        if (lane == 0) { sh[0] = s; sh[1] = s2; }
    }
    __syncthreads();
    float mean = sh[0] * (1.f / Ee);
    float var  = sh[1] * (1.f / Ee) - mean * mean;
    float inv  = rsqrtf(var + 1e-5f);
    for (int i = threadIdx.x; i < Ee; i += 256) {
        float y = (xr[i] - mean) * inv * gamma[i] + beta[i];
        oh[(size_t)row * Ee + i] = __float2half_rn(y);
    }
}

// ---------------- causal softmax, in place on fp16 logits ----------------------
__global__ void softmax_kernel(__half* __restrict__ P)
{
    int t = blockIdx.x, b = blockIdx.y;
    __half* row = P + ((size_t)b * Tt + t) * Tt;
    int n = t + 1;
    const float scale = 0.0220970869120796101f;  // 1/sqrt(2048)
    __shared__ float buf[Tt];                    // 8 KB
    __shared__ float sh[32];
    int w = threadIdx.x >> 5, lane = threadIdx.x & 31;

    for (int i = threadIdx.x; i < n; i += 256) buf[i] = __half2float(row[i]);
    __syncthreads();

    float mx = -3.4e38f;
    for (int i = threadIdx.x; i < n; i += 256) mx = fmaxf(mx, buf[i]);
    #pragma unroll
    for (int off = 16; off; off >>= 1) mx = fmaxf(mx, __shfl_xor_sync(0xffffffffu, mx, off));
    if (lane == 0) sh[w] = mx;
    __syncthreads();
    if (w == 0) {
        mx = (lane < 8) ? sh[lane] : -3.4e38f;
        #pragma unroll
        for (int off = 4; off; off >>= 1) mx = fmaxf(mx, __shfl_xor_sync(0xffffffffu, mx, off));
        if (lane == 0) sh[0] = mx;
    }
    __syncthreads();
    mx = sh[0];
    __syncthreads();

    float sum = 0.f;
    for (int i = threadIdx.x; i < n; i += 256) sum += __expf((buf[i] - mx) * scale);
    #pragma unroll
    for (int off = 16; off; off >>= 1) sum += __shfl_xor_sync(0xffffffffu, sum, off);
    if (lane == 0) sh[w] = sum;
    __syncthreads();
    if (w == 0) {
        sum = (lane < 8) ? sh[lane] : 0.f;
        #pragma unroll
        for (int off = 4; off; off >>= 1) sum += __shfl_xor_sync(0xffffffffu, sum, off);
        if (lane == 0) sh[0] = sum;
    }
    __syncthreads();
    float inv = 1.f / sh[0];

    for (int i = threadIdx.x; i < Tt; i += 256) {
        float p = (i < n) ? __expf((buf[i] - mx) * scale) * inv : 0.f;
        row[i] = __float2half_rn(p);
    }
}

// ---------------- launch -------------------------------------------------------
extern "C" void kernel_launch(void* const* d_in, const int* in_sizes, int n_in,
                              void* d_out, int out_size)
{
    const float* x      = (const float*)d_in[0];
    const float* gamma1 = (const float*)d_in[1];
    const float* beta1  = (const float*)d_in[2];
    const float* Wq     = (const float*)d_in[3];
    const float* Wk     = (const float*)d_in[4];
    const float* Wv     = (const float*)d_in[5];
    const float* Wo     = (const float*)d_in[6];
    const float* bo     = (const float*)d_in[7];
    const float* gamma2 = (const float*)d_in[8];
    const float* beta2  = (const float*)d_in[9];
    const float* W1     = (const float*)d_in[10];
    const float* b1     = (const float*)d_in[11];
    const float* W2     = (const float*)d_in[12];
    const float* b2     = (const float*)d_in[13];
    float* out = (float*)d_out;

    float *x1;
    __half *hh, *qkv, *ph, *ath, *ffh, *wh;
    cudaGetSymbolAddress((void**)&x1,  g_x1);
    cudaGetSymbolAddress((void**)&hh,  g_hh);
    cudaGetSymbolAddress((void**)&qkv, g_qkv);
    cudaGetSymbolAddress((void**)&ph,  g_ph);
    cudaGetSymbolAddress((void**)&ath, g_ath);
    cudaGetSymbolAddress((void**)&ffh, g_ffh);
    cudaGetSymbolAddress((void**)&wh,  g_wh);

    cudaFuncSetAttribute(hgemm<false, 0, false>, cudaFuncAttributeMaxDynamicSharedMemorySize, HSMEM);
    cudaFuncSetAttribute(hgemm<false, 1, false>, cudaFuncAttributeMaxDynamicSharedMemorySize, HSMEM);
    cudaFuncSetAttribute(hgemm<false, 1, true>,  cudaFuncAttributeMaxDynamicSharedMemorySize, HSMEM);
    cudaFuncSetAttribute(hgemm<true,  1, false>, cudaFuncAttributeMaxDynamicSharedMemorySize, HSMEM);

    const size_t oW1 = (size_t)4 * EE, oW2 = (size_t)4 * EE + (size_t)FFF * Ee;
    const size_t totalW = (size_t)4 * EE + 2 * (size_t)FFF * Ee;   // 50,331,648

    // 0) fused weight rounding (fp32 -> fp16) in ONE launch
    cvt6_kernel<<<(unsigned)(totalW / 1024), 256>>>(Wq, Wk, Wv, Wo, W1, W2, wh);

    // 1) LN1 -> fp16
    ln_kernel<<<MR, 256>>>(x, gamma1, beta1, hh);

    // 2) fused QKV projection: [MR, E] x [3E, E]^T -> qkv [MR, 6144]
    dim3 gQKV(QKVN / 128, MR / 128, 1);
    hgemm<false, 1, false><<<gQKV, 256, HSMEM>>>(hh, wh, nullptr, nullptr, nullptr, qkv,
                                                 QKVN, Ee, Ee, Ee, QKVN, 0, 0, 0, 0);

    // 3) raw logits = q k^T -> fp16 ph (packed triangular grid: 136 tiles/batch)
    dim3 gQK(136, 1, Bb);
    hgemm<false, 1, false><<<gQK, 256, HSMEM>>>(qkv, qkv + 2048, nullptr, nullptr, nullptr, ph,
                                                Tt, Ee, QKVN, QKVN, Tt,
                                                (size_t)Tt * QKVN, (size_t)Tt * QKVN, (size_t)Tt * Tt, 3);

    // 4) causal softmax in place on ph (single gmem read pass via smem staging)
    softmax_kernel<<<dim3(Tt, Bb), 256>>>(ph);

    // 5) attn = P @ V (NN, K clamped at diagonal, reversed y) -> fp16
    dim3 gPV(Ee / 128, Tt / 128, Bb);
    hgemm<true, 1, false><<<gPV, 256, HSMEM>>>(ph, qkv + 4096, nullptr, nullptr, nullptr, ath,
                                               Ee, Tt, Tt, QKVN, Ee,
                                               (size_t)Tt * Tt, (size_t)Tt * QKVN, (size_t)Tt * Ee, 2);

    // 6) x1 = attn Wo^T + bo + x (fp32)
    dim3 gProj(Ee / 128, MR / 128, 1);
    hgemm<false, 0, false><<<gProj, 256, HSMEM>>>(ath, wh + 3 * EE, bo, x, x1, nullptr,
                                                  Ee, Ee, Ee, Ee, Ee, 0, 0, 0, 0);

    // 7) LN2 -> fp16
    ln_kernel<<<MR, 256>>>(x1, gamma2, beta2, hh);

    // 8) ff = relu(h W1^T + b1) -> fp16
    dim3 gFF1(FFF / 128, MR / 128, 1);
    hgemm<false, 1, true><<<gFF1, 256, HSMEM>>>(hh, wh + oW1, b1, nullptr, nullptr, ffh,
                                                FFF, Ee, Ee, Ee, FFF, 0, 0, 0, 0);

    // 9) out = ff W2^T + b2 + x1 (fp32)
    dim3 gFF2(Ee / 128, MR / 128, 1);
    hgemm<false, 0, false><<<gFF2, 256, HSMEM>>>(ffh, wh + oW2, b2, x1, out, nullptr,
                                                 Ee, FFF, FFF, FFF, Ee, 0, 0, 0, 0);
}